// round 7
// baseline (speedup 1.0000x reference)
#include <cuda_runtime.h>
#include <cuda_fp16.h>
#include <cstdint>

#define D_MODEL 1024
#define N_HEADS 16
#define D_K     64
#define SEQ     2048
#define BSZ     2
#define M_TOK   (BSZ * SEQ)   // 4096 tokens

// ---------------------------------------------------------------------------
// fp16 arena (device global: allocation-free rule). 64M halves = 128 MB.
// ---------------------------------------------------------------------------
#define MEG (1048576ULL)
__device__ __half g_hf[64 * MEG];

static const size_t OFF_IQH = 0,        OFF_IQL = 4 * MEG;
static const size_t OFF_IKH = 8 * MEG,  OFF_IKL = 12 * MEG;
static const size_t OFF_IVH = 16 * MEG, OFF_IVL = 20 * MEG;
static const size_t OFF_WQH = 24 * MEG, OFF_WQL = 25 * MEG;
static const size_t OFF_WKH = 26 * MEG, OFF_WKL = 27 * MEG;
static const size_t OFF_WVH = 28 * MEG, OFF_WVL = 29 * MEG;
static const size_t OFF_WOH = 30 * MEG, OFF_WOL = 31 * MEG;
static const size_t OFF_PQH = 32 * MEG, OFF_PQL = 36 * MEG;
static const size_t OFF_PKH = 40 * MEG, OFF_PKL = 44 * MEG;
static const size_t OFF_PVH = 48 * MEG, OFF_PVL = 52 * MEG;
static const size_t OFF_OH = 56 * MEG,  OFF_OL = 60 * MEG;

// ---------------------------------------------------------------------------
// PTX wrappers (baseline PTX — compiles at compute_103)
// ---------------------------------------------------------------------------
__device__ __forceinline__ uint32_t smem_u32(const void* p) {
    uint32_t a;
    asm("{ .reg .u64 t; cvta.to.shared.u64 t, %1; cvt.u32.u64 %0, t; }"
        : "=r"(a) : "l"(p));
    return a;
}
__device__ __forceinline__ void ldsm_x4(uint32_t* r, uint32_t addr) {
    asm volatile("ldmatrix.sync.aligned.m8n8.x4.shared.b16 {%0,%1,%2,%3}, [%4];"
                 : "=r"(r[0]), "=r"(r[1]), "=r"(r[2]), "=r"(r[3]) : "r"(addr));
}
__device__ __forceinline__ void ldsm_x2(uint32_t* r, uint32_t addr) {
    asm volatile("ldmatrix.sync.aligned.m8n8.x2.shared.b16 {%0,%1}, [%2];"
                 : "=r"(r[0]), "=r"(r[1]) : "r"(addr));
}
__device__ __forceinline__ void ldsm_x2_t(uint32_t* r, uint32_t addr) {
    asm volatile("ldmatrix.sync.aligned.m8n8.x2.trans.shared.b16 {%0,%1}, [%2];"
                 : "=r"(r[0]), "=r"(r[1]) : "r"(addr));
}
__device__ __forceinline__ void mma16816(float* d, const uint32_t* a, const uint32_t* b) {
    asm volatile(
        "mma.sync.aligned.m16n8k16.row.col.f32.f16.f16.f32 "
        "{%0,%1,%2,%3}, {%4,%5,%6,%7}, {%8,%9}, {%0,%1,%2,%3};"
        : "+f"(d[0]), "+f"(d[1]), "+f"(d[2]), "+f"(d[3])
        : "r"(a[0]), "r"(a[1]), "r"(a[2]), "r"(a[3]), "r"(b[0]), "r"(b[1]));
}
__device__ __forceinline__ void cp16(uint32_t saddr, const void* g) {
    asm volatile("cp.async.cg.shared.global [%0], [%1], 16;"
                 :: "r"(saddr), "l"(g));
}
#define CP_COMMIT() asm volatile("cp.async.commit_group;" ::: "memory")
#define CP_WAIT0()  asm volatile("cp.async.wait_group 0;" ::: "memory")

// ---------------------------------------------------------------------------
// Fused split: all 7 tensors in ONE launch.
// ---------------------------------------------------------------------------
struct SplitArgs {
    const float* src[7];
    __half* hi[7];
    __half* lo[7];
};

__global__ __launch_bounds__(256)
void split_all(SplitArgs a)
{
    int blk = blockIdx.x;
    int seg, rel;
    if (blk < 12288) { seg = blk >> 12; rel = blk & 4095; }
    else             { seg = 3 + ((blk - 12288) >> 10); rel = (blk - 12288) & 1023; }
    int i = rel * 256 + threadIdx.x;

    float4 v = ((const float4*)a.src[seg])[i];
    __half h0 = __float2half_rn(v.x), h1 = __float2half_rn(v.y);
    __half h2 = __float2half_rn(v.z), h3 = __float2half_rn(v.w);
    __half2 ph0; ph0.x = h0; ph0.y = h1;
    __half2 ph1; ph1.x = h2; ph1.y = h3;
    __half2 pl0; pl0.x = __float2half_rn(v.x - __half2float(h0));
    pl0.y = __float2half_rn(v.y - __half2float(h1));
    __half2 pl1; pl1.x = __float2half_rn(v.z - __half2float(h2));
    pl1.y = __float2half_rn(v.w - __half2float(h3));
    ((__half2*)a.hi[seg])[i * 2 + 0] = ph0;
    ((__half2*)a.hi[seg])[i * 2 + 1] = ph1;
    ((__half2*)a.lo[seg])[i * 2 + 0] = pl0;
    ((__half2*)a.lo[seg])[i * 2 + 1] = pl1;
}

// ---------------------------------------------------------------------------
// Tensor-core split-fp16 GEMM core (2-stage cp.async, 1 sync/iter, 2 CTA/SM).
// CTA 128x128, BK=32, 256 threads, warp tile 64x32.
// ---------------------------------------------------------------------------
#define SP 40                       // smem row stride in halves (80B = 5x16B)
#define TSZB (128 * SP * 2)         // bytes per tile (10240)
#define STGB (4 * TSZB)             // bytes per stage (40960)
#define GSMEM (2 * STGB)            // 81920

struct GemmOne {
    const __half* Ah; const __half* Al;
    const __half* Bh; const __half* Bl;
    const float* bias;
    __half* Ch; __half* Cl;      // MODE 1 outputs
    float* C;                    // MODE 0 output
    float scale;
};
struct GemmQKV { GemmOne g[3]; };

template<int MODE>
__device__ __forceinline__ void gemm_core(const GemmOne& P, int bm, int bn)
{
    extern __shared__ __align__(16) char dsm[];
    const uint32_t base = smem_u32(dsm);
    const int tid  = threadIdx.x;
    const int wid  = tid >> 5;
    const int lane = tid & 31;
    const int wm = (wid >> 2) * 64;
    const int wn = (wid & 3) * 32;

    float acc[4][4][4];
#pragma unroll
    for (int i = 0; i < 4; i++)
#pragma unroll
        for (int j = 0; j < 4; j++)
#pragma unroll
            for (int r = 0; r < 4; r++) acc[i][j][r] = 0.f;

    const int arow = lane & 15;
    const int acol = (lane >> 4) * 8;
    const int brow = lane & 7;
    const int bcol = ((lane & 15) >> 3) * 8;

    auto load_stage = [&](int stg, int k0) {
        uint32_t sb = base + stg * STGB;
#pragma unroll
        for (int j = 0; j < 2; j++) {
            int c    = tid + j * 256;
            int row  = c >> 2;
            int kcol = (c & 3) * 8;
            size_t ga = (size_t)(bm + row) * D_MODEL + k0 + kcol;
            size_t gb = (size_t)(bn + row) * D_MODEL + k0 + kcol;
            uint32_t so = (uint32_t)(row * SP + kcol) * 2;
            cp16(sb + 0 * TSZB + so, &P.Ah[ga]);
            cp16(sb + 1 * TSZB + so, &P.Al[ga]);
            cp16(sb + 2 * TSZB + so, &P.Bh[gb]);
            cp16(sb + 3 * TSZB + so, &P.Bl[gb]);
        }
    };

    load_stage(0, 0);
    CP_COMMIT();

    for (int kc = 0; kc < 32; kc++) {
        const int cur = kc & 1;
        CP_WAIT0();
        __syncthreads();
        if (kc < 31) {
            load_stage(cur ^ 1, (kc + 1) * 32);
            CP_COMMIT();
        }

        const uint32_t uAh = base + cur * STGB;
        const uint32_t uAl = uAh + TSZB;
        const uint32_t uBh = uAh + 2 * TSZB;
        const uint32_t uBl = uAh + 3 * TSZB;

        // Sequenced passes to limit live fragment registers:
        //   pass1: Ahi*Bhi   pass2: Alo*Bhi   pass3: Ahi*Blo
#pragma unroll
        for (int ks = 0; ks < 2; ks++) {
            uint32_t ah[4][4];
            uint32_t bb[4][2];
#pragma unroll
            for (int mt = 0; mt < 4; mt++) {
                uint32_t off = ((wm + mt * 16 + arow) * SP + ks * 16 + acol) * 2;
                ldsm_x4(ah[mt], uAh + off);
            }
#pragma unroll
            for (int nt = 0; nt < 4; nt++) {
                uint32_t off = ((wn + nt * 8 + brow) * SP + ks * 16 + bcol) * 2;
                ldsm_x2(bb[nt], uBh + off);
            }
#pragma unroll
            for (int mt = 0; mt < 4; mt++)
#pragma unroll
                for (int nt = 0; nt < 4; nt++)
                    mma16816(acc[mt][nt], ah[mt], bb[nt]);

            {
                uint32_t al[4][4];
#pragma unroll
                for (int mt = 0; mt < 4; mt++) {
                    uint32_t off = ((wm + mt * 16 + arow) * SP + ks * 16 + acol) * 2;
                    ldsm_x4(al[mt], uAl + off);
                }
#pragma unroll
                for (int mt = 0; mt < 4; mt++)
#pragma unroll
                    for (int nt = 0; nt < 4; nt++)
                        mma16816(acc[mt][nt], al[mt], bb[nt]);
            }

#pragma unroll
            for (int nt = 0; nt < 4; nt++) {
                uint32_t off = ((wn + nt * 8 + brow) * SP + ks * 16 + bcol) * 2;
                ldsm_x2(bb[nt], uBl + off);
            }
#pragma unroll
            for (int mt = 0; mt < 4; mt++)
#pragma unroll
                for (int nt = 0; nt < 4; nt++)
                    mma16816(acc[mt][nt], ah[mt], bb[nt]);
        }
    }

#pragma unroll
    for (int mt = 0; mt < 4; mt++) {
#pragma unroll
        for (int half = 0; half < 2; half++) {
            int m = bm + wm + mt * 16 + (lane >> 2) + half * 8;
            int b = m >> 11, s = m & 2047;
#pragma unroll
            for (int nt = 0; nt < 4; nt++) {
                int n = bn + wn + nt * 8 + 2 * (lane & 3);
                float vx = (acc[mt][nt][half * 2 + 0] + P.bias[n + 0]) * P.scale;
                float vy = (acc[mt][nt][half * 2 + 1] + P.bias[n + 1]) * P.scale;
                if (MODE == 1) {
                    int h = n >> 6, dd = n & 63;
                    size_t co = ((size_t)(b * N_HEADS + h) * SEQ + s) * D_K + dd;
                    __half hx = __float2half_rn(vx), hy = __float2half_rn(vy);
                    __half2 hh; hh.x = hx; hh.y = hy;
                    __half2 ll;
                    ll.x = __float2half_rn(vx - __half2float(hx));
                    ll.y = __float2half_rn(vy - __half2float(hy));
                    *(__half2*)&P.Ch[co] = hh;
                    *(__half2*)&P.Cl[co] = ll;
                } else {
                    float2 v; v.x = vx; v.y = vy;
                    *(float2*)&P.C[(size_t)m * D_MODEL + n] = v;
                }
            }
        }
    }
}

__global__ __launch_bounds__(256, 2)
void gemm_qkv(GemmQKV P)
{
    gemm_core<1>(P.g[blockIdx.z], blockIdx.y * 128, blockIdx.x * 128);
}

__global__ __launch_bounds__(256, 2)
void gemm_o(GemmOne P)
{
    gemm_core<0>(P, blockIdx.y * 128, blockIdx.x * 128);
}

// ---------------------------------------------------------------------------
// Flash attention, mma.sync fp16-split, 2-stage cp.async, 3 CTA/SM target.
// ---------------------------------------------------------------------------
#define ST 72
#define FTSZB (64 * ST * 2)
#define FSTGB (4 * FTSZB)
#define FSMEM (2 * FSTGB)            // 73728

__global__ __launch_bounds__(128, 3)
void flash_mma(const __half* __restrict__ Qh, const __half* __restrict__ Ql,
               const __half* __restrict__ Kh, const __half* __restrict__ Kl,
               const __half* __restrict__ Vh, const __half* __restrict__ Vl,
               __half* __restrict__ Oh, __half* __restrict__ Ol)
{
    extern __shared__ __align__(16) char fsm[];
    const uint32_t base = smem_u32(fsm);

    const int bh  = blockIdx.y;
    const int q0  = blockIdx.x * 64;
    const int tid = threadIdx.x;
    const int w   = tid >> 5;
    const int lane = tid & 31;
    const size_t bhoff = (size_t)bh * SEQ * D_K;

    // ---- stage Q in buffer 1, extract A-fragments ----
    {
        __half* sQh = (__half*)(fsm + FSTGB);
        __half* sQl = (__half*)(fsm + FSTGB + FTSZB);
#pragma unroll
        for (int it = 0; it < 4; it++) {
            int idx = tid + it * 128;
            int row = idx >> 3, c8 = (idx & 7) * 8;
            size_t g = bhoff + (size_t)(q0 + row) * D_K + c8;
            *(uint4*)&sQh[row * ST + c8] = *(const uint4*)&Qh[g];
            *(uint4*)&sQl[row * ST + c8] = *(const uint4*)&Ql[g];
        }
    }
    __syncthreads();
    uint32_t qh[4][4], ql[4][4];
    {
        const uint32_t uQh = base + FSTGB, uQl = base + FSTGB + FTSZB;
        const int arow = lane & 15, acol = (lane >> 4) * 8;
#pragma unroll
        for (int ks = 0; ks < 4; ks++) {
            uint32_t off = ((w * 16 + arow) * ST + ks * 16 + acol) * 2;
            ldsm_x4(qh[ks], uQh + off);
            ldsm_x4(ql[ks], uQl + off);
        }
    }
    __syncthreads();

    auto load_kv = [&](int stg, int kv0) {
        uint32_t sb = base + stg * FSTGB;
#pragma unroll
        for (int it = 0; it < 4; it++) {
            int idx = tid + it * 128;
            int row = idx >> 3, c8 = (idx & 7) * 8;
            size_t g = bhoff + (size_t)(kv0 + row) * D_K + c8;
            uint32_t so = (uint32_t)(row * ST + c8) * 2;
            cp16(sb + 0 * FTSZB + so, &Kh[g]);
            cp16(sb + 1 * FTSZB + so, &Kl[g]);
            cp16(sb + 2 * FTSZB + so, &Vh[g]);
            cp16(sb + 3 * FTSZB + so, &Vl[g]);
        }
    };

    float o[8][4];
#pragma unroll
    for (int i = 0; i < 8; i++)
#pragma unroll
        for (int r = 0; r < 4; r++) o[i][r] = 0.f;
    float mA = -1e30f, mB = -1e30f, lA = 0.f, lB = 0.f;

    load_kv(0, 0);
    CP_COMMIT();

    for (int t = 0; t < SEQ / 64; t++) {
        const int cur = t & 1;
        CP_WAIT0();
        __syncthreads();
        if (t < SEQ / 64 - 1) {
            load_kv(cur ^ 1, (t + 1) * 64);
            CP_COMMIT();
        }

        const uint32_t uKh = base + cur * FSTGB;
        const uint32_t uKl = uKh + FTSZB;
        const uint32_t uVh = uKh + 2 * FTSZB;
        const uint32_t uVl = uKh + 3 * FTSZB;

        // ---- S = Q . K^T ----
        float s[8][4];
#pragma unroll
        for (int i = 0; i < 8; i++)
#pragma unroll
            for (int r = 0; r < 4; r++) s[i][r] = 0.f;

        const int brow = lane & 7;
        const int bcol = ((lane & 15) >> 3) * 8;
#pragma unroll
        for (int ks = 0; ks < 4; ks++) {
            uint32_t kh[8][2], kl[8][2];
#pragma unroll
            for (int nt = 0; nt < 8; nt++) {
                uint32_t off = ((nt * 8 + brow) * ST + ks * 16 + bcol) * 2;
                ldsm_x2(kh[nt], uKh + off);
                ldsm_x2(kl[nt], uKl + off);
            }
#pragma unroll
            for (int nt = 0; nt < 8; nt++) mma16816(s[nt], qh[ks], kh[nt]);
#pragma unroll
            for (int nt = 0; nt < 8; nt++) mma16816(s[nt], ql[ks], kh[nt]);
#pragma unroll
            for (int nt = 0; nt < 8; nt++) mma16816(s[nt], qh[ks], kl[nt]);
        }

        // ---- online softmax (log2 domain) ----
        float tA = -1e30f, tB = -1e30f;
#pragma unroll
        for (int nt = 0; nt < 8; nt++) {
            tA = fmaxf(tA, fmaxf(s[nt][0], s[nt][1]));
            tB = fmaxf(tB, fmaxf(s[nt][2], s[nt][3]));
        }
        tA = fmaxf(tA, __shfl_xor_sync(0xffffffff, tA, 1));
        tA = fmaxf(tA, __shfl_xor_sync(0xffffffff, tA, 2));
        tB = fmaxf(tB, __shfl_xor_sync(0xffffffff, tB, 1));
        tB = fmaxf(tB, __shfl_xor_sync(0xffffffff, tB, 2));
        float mnA = fmaxf(mA, tA), mnB = fmaxf(mB, tB);
        float cA = exp2f(mA - mnA), cB = exp2f(mB - mnB);
        lA *= cA; lB *= cB;
#pragma unroll
        for (int nt = 0; nt < 8; nt++) {
            o[nt][0] *= cA; o[nt][1] *= cA;
            o[nt][2] *= cB; o[nt][3] *= cB;
        }
        mA = mnA; mB = mnB;

        // ---- P = exp2(S - m), split hi/lo in registers ----
        uint32_t pAh[8], pAl[8], pBh[8], pBl[8];
#pragma unroll
        for (int nt = 0; nt < 8; nt++) {
            float p0 = exp2f(s[nt][0] - mnA);
            float p1 = exp2f(s[nt][1] - mnA);
            float p2 = exp2f(s[nt][2] - mnB);
            float p3 = exp2f(s[nt][3] - mnB);
            lA += p0 + p1; lB += p2 + p3;
            __half h0 = __float2half_rn(p0), h1 = __float2half_rn(p1);
            __half h2 = __float2half_rn(p2), h3 = __float2half_rn(p3);
            __half2 tt;
            tt.x = h0; tt.y = h1; pAh[nt] = *(uint32_t*)&tt;
            tt.x = h2; tt.y = h3; pBh[nt] = *(uint32_t*)&tt;
            tt.x = __float2half_rn(p0 - __half2float(h0));
            tt.y = __float2half_rn(p1 - __half2float(h1));
            pAl[nt] = *(uint32_t*)&tt;
            tt.x = __float2half_rn(p2 - __half2float(h2));
            tt.y = __float2half_rn(p3 - __half2float(h3));
            pBl[nt] = *(uint32_t*)&tt;
        }

        // ---- O += P . V ----
#pragma unroll
        for (int ks = 0; ks < 4; ks++) {
            uint32_t aPh[4] = { pAh[2 * ks], pBh[2 * ks], pAh[2 * ks + 1], pBh[2 * ks + 1] };
            uint32_t aPl[4] = { pAl[2 * ks], pBl[2 * ks], pAl[2 * ks + 1], pBl[2 * ks + 1] };
            uint32_t vh[8][2], vl[8][2];
#pragma unroll
            for (int ntd = 0; ntd < 8; ntd++) {
                uint32_t off = ((ks * 16 + (lane & 15)) * ST + ntd * 8) * 2;
                ldsm_x2_t(vh[ntd], uVh + off);
                ldsm_x2_t(vl[ntd], uVl + off);
            }
#pragma unroll
            for (int ntd = 0; ntd < 8; ntd++) mma16816(o[ntd], aPh, vh[ntd]);
#pragma unroll
            for (int ntd = 0; ntd < 8; ntd++) mma16816(o[ntd], aPl, vh[ntd]);
#pragma unroll
            for (int ntd = 0; ntd < 8; ntd++) mma16816(o[ntd], aPh, vl[ntd]);
        }
    }

    // ---- finalize ----
    lA += __shfl_xor_sync(0xffffffff, lA, 1);
    lA += __shfl_xor_sync(0xffffffff, lA, 2);
    lB += __shfl_xor_sync(0xffffffff, lB, 1);
    lB += __shfl_xor_sync(0xffffffff, lB, 2);
    float invA = 1.f / lA, invB = 1.f / lB;

    const int b = bh >> 4, h = bh & 15;
    const int rowA = q0 + w * 16 + (lane >> 2);
    const int rowB = rowA + 8;
    const int c2 = 2 * (lane & 3);
#pragma unroll
    for (int ntd = 0; ntd < 8; ntd++) {
        float v0 = o[ntd][0] * invA, v1 = o[ntd][1] * invA;
        float v2 = o[ntd][2] * invB, v3 = o[ntd][3] * invB;
        size_t offA = (size_t)(b * SEQ + rowA) * D_MODEL + h * D_K + ntd * 8 + c2;
        size_t offB = (size_t)(b * SEQ + rowB) * D_MODEL + h * D_K + ntd * 8 + c2;
        __half h0 = __float2half_rn(v0), h1 = __float2half_rn(v1);
        __half h2 = __float2half_rn(v2), h3 = __float2half_rn(v3);
        __half2 t2;
        t2.x = h0; t2.y = h1; *(__half2*)&Oh[offA] = t2;
        t2.x = __float2half_rn(v0 - __half2float(h0));
        t2.y = __float2half_rn(v1 - __half2float(h1));
        *(__half2*)&Ol[offA] = t2;
        t2.x = h2; t2.y = h3; *(__half2*)&Oh[offB] = t2;
        t2.x = __float2half_rn(v2 - __half2float(h2));
        t2.y = __float2half_rn(v3 - __half2float(h3));
        *(__half2*)&Ol[offB] = t2;
    }
}

// ---------------------------------------------------------------------------
// Launch
// ---------------------------------------------------------------------------
extern "C" void kernel_launch(void* const* d_in, const int* in_sizes, int n_in,
                              void* d_out, int out_size)
{
    const float* q   = (const float*)d_in[0];
    const float* k   = (const float*)d_in[1];
    const float* v   = (const float*)d_in[2];
    const float* W_q = (const float*)d_in[3];
    const float* b_q = (const float*)d_in[4];
    const float* W_k = (const float*)d_in[5];
    const float* b_k = (const float*)d_in[6];
    const float* W_v = (const float*)d_in[7];
    const float* b_v = (const float*)d_in[8];
    const float* W_o = (const float*)d_in[9];
    const float* b_o = (const float*)d_in[10];
    float* out = (float*)d_out;

    __half* hf;
    cudaGetSymbolAddress((void**)&hf, g_hf);

    cudaFuncSetAttribute((void*)gemm_qkv, cudaFuncAttributeMaxDynamicSharedMemorySize, GSMEM);
    cudaFuncSetAttribute((void*)gemm_o,   cudaFuncAttributeMaxDynamicSharedMemorySize, GSMEM);
    cudaFuncSetAttribute((void*)flash_mma, cudaFuncAttributeMaxDynamicSharedMemorySize, FSMEM);

    SplitArgs sa;
    sa.src[0] = q;   sa.hi[0] = hf + OFF_IQH; sa.lo[0] = hf + OFF_IQL;
    sa.src[1] = k;   sa.hi[1] = hf + OFF_IKH; sa.lo[1] = hf + OFF_IKL;
    sa.src[2] = v;   sa.hi[2] = hf + OFF_IVH; sa.lo[2] = hf + OFF_IVL;
    sa.src[3] = W_q; sa.hi[3] = hf + OFF_WQH; sa.lo[3] = hf + OFF_WQL;
    sa.src[4] = W_k; sa.hi[4] = hf + OFF_WKH; sa.lo[4] = hf + OFF_WKL;
    sa.src[5] = W_v; sa.hi[5] = hf + OFF_WVH; sa.lo[5] = hf + OFF_WVL;
    sa.src[6] = W_o; sa.hi[6] = hf + OFF_WOH; sa.lo[6] = hf + OFF_WOL;
    split_all<<<16384, 256>>>(sa);

    const float qscale = 0.125f * 1.4426950408889634f;
    GemmQKV gp;
    gp.g[0] = { hf + OFF_IQH, hf + OFF_IQL, hf + OFF_WQH, hf + OFF_WQL, b_q,
                hf + OFF_PQH, hf + OFF_PQL, nullptr, qscale };
    gp.g[1] = { hf + OFF_IKH, hf + OFF_IKL, hf + OFF_WKH, hf + OFF_WKL, b_k,
                hf + OFF_PKH, hf + OFF_PKL, nullptr, 1.0f };
    gp.g[2] = { hf + OFF_IVH, hf + OFF_IVL, hf + OFF_WVH, hf + OFF_WVL, b_v,
                hf + OFF_PVH, hf + OFF_PVL, nullptr, 1.0f };
    dim3 ggrid(D_MODEL / 128, M_TOK / 128, 3);   // (8, 32, 3)
    gemm_qkv<<<ggrid, 256, GSMEM>>>(gp);

    dim3 agrid(SEQ / 64, BSZ * N_HEADS);         // (32, 32)
    flash_mma<<<agrid, 128, FSMEM>>>(hf + OFF_PQH, hf + OFF_PQL,
                                     hf + OFF_PKH, hf + OFF_PKL,
                                     hf + OFF_PVH, hf + OFF_PVL,
                                     hf + OFF_OH, hf + OFF_OL);

    GemmOne go = { hf + OFF_OH, hf + OFF_OL, hf + OFF_WOH, hf + OFF_WOL, b_o,
                   nullptr, nullptr, out, 1.0f };
    dim3 ogrid(D_MODEL / 128, M_TOK / 128, 1);
    gemm_o<<<ogrid, 256, GSMEM>>>(go);
}